// round 1
// baseline (speedup 1.0000x reference)
#include <cuda_runtime.h>
#include <math.h>

// Problem constants
#define BB    8
#define TTT   8
#define BT    64        // B*T
#define HH    512
#define E2D   512
#define NPIX  49
#define CDIM  2048
#define VOCAB 10000
#define DSPLIT 4

// ---------------- scratch (device globals; no allocation allowed) ----------
__device__ float g_s[BT*HH];
__device__ float g_g2[BT*HH];
__device__ float g_fm[BB*CDIM];
__device__ float g_alpha0[BT*CDIM];     // cxt, then softmaxed in place
__device__ float g_g[BT*NPIX];
__device__ float g_cs[BT*NPIX];
__device__ float g_Mpart[DSPLIT*BT*NPIX*NPIX];
__device__ float g_cchan[BT*NPIX];
__device__ float g_alpha_t[BT*NPIX];
__device__ float g_cspat[BT*CDIM];
__device__ float g_sgate[BT*HH];
__device__ float g_cgate[BT*HH];
__device__ float g_chat[BT*HH];         // c_hat + h (ready for MLP)

__device__ __forceinline__ float tanh_fast(float x) {
    float y;
    asm("tanh.approx.f32 %0, %1;" : "=f"(y) : "f"(x));
    return y;
}
__device__ __forceinline__ float sigmoidf_(float x) {
    return 1.0f / (1.0f + expf(-x));
}

// ---------------------------------------------------------------------------
// s = sigmoid(x@Wsx + hprev@Wsh) * tanh(cells)      [64,512]
// grid (8 ntiles, 8 mtiles), 256 thr. TM=8, TN=64; thread: 1 col x 2 rows.
// ---------------------------------------------------------------------------
__global__ void s_kernel(const float* __restrict__ x,
                         const float* __restrict__ hiddens,
                         const float* __restrict__ cells,
                         const float* __restrict__ Wsx,
                         const float* __restrict__ Wsh) {
    __shared__ float As[8][64];
    const int n0 = blockIdx.x * 64, m0 = blockIdx.y * 8;
    const int col = n0 + (threadIdx.x & 63);
    const int rl  = (threadIdx.x >> 6) * 2;
    const int r0  = m0 + rl;
    float acc0 = 0.f, acc1 = 0.f;
    for (int phase = 0; phase < 2; ++phase) {
        const float* A = phase ? hiddens : x;
        const float* W = phase ? Wsh : Wsx;
        for (int k0 = 0; k0 < 512; k0 += 64) {
            __syncthreads();
            for (int i = threadIdx.x; i < 512; i += 256) {
                int r = m0 + (i >> 6), kk = i & 63;
                float v;
                if (phase == 1) v = (r & 7) ? A[(r - 1) * 512 + k0 + kk] : 0.f;
                else            v = A[r * 512 + k0 + kk];
                As[i >> 6][kk] = v;
            }
            __syncthreads();
            #pragma unroll 8
            for (int kk = 0; kk < 64; kk++) {
                float w = W[(k0 + kk) * 512 + col];
                acc0 += As[rl][kk] * w;
                acc1 += As[rl + 1][kk] * w;
            }
        }
    }
    g_s[r0 * 512 + col]       = sigmoidf_(acc0) * tanhf(cells[r0 * 512 + col]);
    g_s[(r0 + 1) * 512 + col] = sigmoidf_(acc1) * tanhf(cells[(r0 + 1) * 512 + col]);
}

// ---------------------------------------------------------------------------
// g2 = h @ Wg2   [64,512]
// ---------------------------------------------------------------------------
__global__ void g2_kernel(const float* __restrict__ hiddens,
                          const float* __restrict__ Wg2) {
    __shared__ float As[8][64];
    const int n0 = blockIdx.x * 64, m0 = blockIdx.y * 8;
    const int col = n0 + (threadIdx.x & 63);
    const int rl  = (threadIdx.x >> 6) * 2;
    const int r0  = m0 + rl;
    float acc0 = 0.f, acc1 = 0.f;
    for (int k0 = 0; k0 < 512; k0 += 64) {
        __syncthreads();
        for (int i = threadIdx.x; i < 512; i += 256) {
            int r = m0 + (i >> 6), kk = i & 63;
            As[i >> 6][kk] = hiddens[r * 512 + k0 + kk];
        }
        __syncthreads();
        #pragma unroll 8
        for (int kk = 0; kk < 64; kk++) {
            float w = Wg2[(k0 + kk) * 512 + col];
            acc0 += As[rl][kk] * w;
            acc1 += As[rl + 1][kk] * w;
        }
    }
    g_g2[r0 * 512 + col]       = acc0;
    g_g2[(r0 + 1) * 512 + col] = acc1;
}

// ---------------------------------------------------------------------------
// featmean[b,d] = mean_k V[b,k,d]   (8 x 2048)
// ---------------------------------------------------------------------------
__global__ void featmean_kernel(const float* __restrict__ V) {
    int idx = blockIdx.x * 256 + threadIdx.x;   // 16384 total
    int b = idx >> 11, d = idx & 2047;
    float s = 0.f;
    #pragma unroll 7
    for (int k = 0; k < NPIX; k++) s += V[(b * NPIX + k) * CDIM + d];
    g_fm[idx] = s * (1.0f / 49.0f);
}

// ---------------------------------------------------------------------------
// cxt[b,t,d] = sum_j tanh(fm[b,d]*Wfeat[j] + g2[bt,j]) * Wcxt[j]
// grid (64 bt, 4 dchunk), 256 thr, 2 d per thread.
// ---------------------------------------------------------------------------
__global__ void cxt_kernel(const float* __restrict__ Wfeat,
                           const float* __restrict__ Wcxt) {
    __shared__ float wf[512], wc[512], gr[512];
    const int bt = blockIdx.x, b = bt >> 3;
    for (int i = threadIdx.x; i < 512; i += 256) {
        wf[i] = Wfeat[i];
        wc[i] = Wcxt[i];
        gr[i] = g_g2[bt * 512 + i];
    }
    __syncthreads();
    const int d0 = blockIdx.y * 512;
    int da = d0 + threadIdx.x;
    int db = da + 256;
    float a0 = g_fm[b * CDIM + da];
    float a1 = g_fm[b * CDIM + db];
    float acc0 = 0.f, acc1 = 0.f;
    #pragma unroll 4
    for (int j = 0; j < 512; j++) {
        float wfj = wf[j], grj = gr[j], wcj = wc[j];
        acc0 += tanh_fast(fmaf(a0, wfj, grj)) * wcj;
        acc1 += tanh_fast(fmaf(a1, wfj, grj)) * wcj;
    }
    g_alpha0[bt * CDIM + da] = acc0;
    g_alpha0[bt * CDIM + db] = acc1;
}

// ---------------------------------------------------------------------------
// softmax over 2048 per bt (in place on g_alpha0)
// ---------------------------------------------------------------------------
__global__ void softmax2048_kernel() {
    __shared__ float red[256];
    const int bt = blockIdx.x, t = threadIdx.x;
    float* p = g_alpha0 + bt * CDIM;
    float mx = -1e30f;
    for (int i = t; i < CDIM; i += 256) mx = fmaxf(mx, p[i]);
    red[t] = mx; __syncthreads();
    for (int s = 128; s > 0; s >>= 1) { if (t < s) red[t] = fmaxf(red[t], red[t + s]); __syncthreads(); }
    mx = red[0]; __syncthreads();
    float sm = 0.f;
    for (int i = t; i < CDIM; i += 256) { float e = expf(p[i] - mx); p[i] = e; sm += e; }
    red[t] = sm; __syncthreads();
    for (int s = 128; s > 0; s >>= 1) { if (t < s) red[t] += red[t + s]; __syncthreads(); }
    float inv = 1.0f / red[0];
    for (int i = t; i < CDIM; i += 256) p[i] *= inv;
}

// ---------------------------------------------------------------------------
// g = h@Wg [64,49],  cs = s@Ws + g [64,49]
// ---------------------------------------------------------------------------
__global__ void gcs_kernel(const float* __restrict__ hiddens,
                           const float* __restrict__ Wg,
                           const float* __restrict__ Ws) {
    const int bt = blockIdx.x, j = threadIdx.x;
    if (j >= NPIX) return;
    float gg = 0.f, ss = 0.f;
    for (int k = 0; k < 512; k++) {
        float hk = hiddens[bt * 512 + k];
        float sk = g_s[bt * 512 + k];
        gg += hk * Wg[k * NPIX + j];
        ss += sk * Ws[k * NPIX + j];
    }
    g_g[bt * NPIX + j]  = gg;
    g_cs[bt * NPIX + j] = ss + gg;
}

// ---------------------------------------------------------------------------
// Mpart[dp][bt][k][k2] = sum_{d in part} alpha0[bt,d]*V[b,k,d]*Wv[d,k2]
// grid (64 bt, DSPLIT), 224 thr; 14x14 thread grid, 4x4 register tile.
// ---------------------------------------------------------------------------
__global__ void wfwv_kernel(const float* __restrict__ V,
                            const float* __restrict__ Wv) {
    __shared__ float aV[49][65];
    __shared__ float Wvs[64][49];
    __shared__ float as_[512];
    const int bt = blockIdx.x, b = bt >> 3;
    const int dp = blockIdx.y, d0 = dp * 512;
    const int t = threadIdx.x;
    for (int i = t; i < 512; i += 224) as_[i] = g_alpha0[bt * CDIM + d0 + i];
    const int tk = t / 14, tk2 = t % 14;
    const bool active = (t < 196);
    int ki[4], k2i[4];
    #pragma unroll
    for (int i = 0; i < 4; i++) { ki[i] = min(tk * 4 + i, 48); k2i[i] = min(tk2 * 4 + i, 48); }
    float acc[4][4];
    #pragma unroll
    for (int i = 0; i < 4; i++)
        #pragma unroll
        for (int j = 0; j < 4; j++) acc[i][j] = 0.f;
    __syncthreads();
    for (int c = 0; c < 8; c++) {
        __syncthreads();
        for (int i = t; i < 49 * 64; i += 224) {
            int r = i >> 6, dd = i & 63;
            aV[r][dd] = V[(b * NPIX + r) * CDIM + d0 + c * 64 + dd] * as_[c * 64 + dd];
        }
        for (int i = t; i < 64 * 49; i += 224) {
            Wvs[i / 49][i % 49] = Wv[(d0 + c * 64) * NPIX + i];
        }
        __syncthreads();
        if (active) {
            #pragma unroll 4
            for (int dd = 0; dd < 64; dd++) {
                float av[4], wv[4];
                #pragma unroll
                for (int i = 0; i < 4; i++) av[i] = aV[ki[i]][dd];
                #pragma unroll
                for (int j = 0; j < 4; j++) wv[j] = Wvs[dd][k2i[j]];
                #pragma unroll
                for (int i = 0; i < 4; i++)
                    #pragma unroll
                    for (int j = 0; j < 4; j++) acc[i][j] += av[i] * wv[j];
            }
        }
    }
    if (active) {
        #pragma unroll
        for (int i = 0; i < 4; i++) {
            int k = tk * 4 + i;
            if (k >= NPIX) continue;
            #pragma unroll
            for (int j = 0; j < 4; j++) {
                int k2 = tk2 * 4 + j;
                if (k2 < NPIX)
                    g_Mpart[(((size_t)dp * BT + bt) * NPIX + k) * NPIX + k2] = acc[i][j];
            }
        }
    }
}

// ---------------------------------------------------------------------------
// c_channel[bt,k] = mean_d alpha0[bt,d]*V[b,k,d]
// ---------------------------------------------------------------------------
__global__ void cchan_kernel(const float* __restrict__ V) {
    const int bt = blockIdx.x, b = bt >> 3;
    const int w = threadIdx.x >> 5, lane = threadIdx.x & 31;
    for (int k = w; k < NPIX; k += 8) {
        float s = 0.f;
        for (int d = lane; d < CDIM; d += 32)
            s += g_alpha0[bt * CDIM + d] * V[(b * NPIX + k) * CDIM + d];
        #pragma unroll
        for (int o = 16; o > 0; o >>= 1) s += __shfl_down_sync(0xffffffffu, s, o);
        if (lane == 0) g_cchan[bt * NPIX + k] = s * (1.0f / 2048.0f);
    }
}

// ---------------------------------------------------------------------------
// z_t, alpha_t, z_ext, beta per bt
// ---------------------------------------------------------------------------
__global__ void zt_kernel(const float* __restrict__ Wh,
                          float* __restrict__ out_alpha,
                          float* __restrict__ out_beta) {
    __shared__ float wh[NPIX], gg[NPIX], zt[NPIX], css[NPIX];
    const int bt = blockIdx.x, t = threadIdx.x;
    if (t < NPIX) { wh[t] = Wh[t]; gg[t] = g_g[bt * NPIX + t]; css[t] = g_cs[bt * NPIX + t]; }
    __syncthreads();
    if (t < NPIX) {
        float z = 0.f;
        for (int k2 = 0; k2 < NPIX; k2++) {
            size_t base = ((size_t)bt * NPIX + t) * NPIX + k2;
            float m = g_Mpart[base]
                    + g_Mpart[(size_t)1 * BT * NPIX * NPIX + base]
                    + g_Mpart[(size_t)2 * BT * NPIX * NPIX + base]
                    + g_Mpart[(size_t)3 * BT * NPIX * NPIX + base];
            z += tanhf(tanhf(m + gg[k2])) * wh[k2];
        }
        zt[t] = z;
    }
    __syncthreads();
    if (t == 0) {
        float ze = 0.f;
        for (int k2 = 0; k2 < NPIX; k2++) ze += tanhf(css[k2]) * wh[k2];
        float mx = -1e30f;
        for (int k = 0; k < NPIX; k++) mx = fmaxf(mx, zt[k]);
        float sm = 0.f;
        for (int k = 0; k < NPIX; k++) sm += expf(zt[k] - mx);
        float inv = 1.0f / sm;
        for (int k = 0; k < NPIX; k++) {
            float a = expf(zt[k] - mx) * inv;
            g_alpha_t[bt * NPIX + k] = a;
            out_alpha[bt * NPIX + k] = a;
        }
        float mx2 = fmaxf(mx, ze);
        float sm2 = 0.f;
        for (int k = 0; k < NPIX; k++) sm2 += expf(zt[k] - mx2);
        sm2 += expf(ze - mx2);
        out_beta[bt] = expf(ze - mx2) / sm2;
    }
}

// ---------------------------------------------------------------------------
// c_spatial[bt,d] = sum_k alpha_t[bt,k] * V[b,k,d]
// ---------------------------------------------------------------------------
__global__ void cspatial_kernel(const float* __restrict__ V) {
    __shared__ float al[NPIX];
    const int bt = blockIdx.x, b = bt >> 3;
    if (threadIdx.x < NPIX) al[threadIdx.x] = g_alpha_t[bt * NPIX + threadIdx.x];
    __syncthreads();
    const int d = blockIdx.y * 256 + threadIdx.x;
    float s = 0.f;
    #pragma unroll 7
    for (int k = 0; k < NPIX; k++) s += al[k] * V[(b * NPIX + k) * CDIM + d];
    g_cspat[bt * CDIM + d] = s;
}

// ---------------------------------------------------------------------------
// s_gate = sigmoid(s@Wgvs + h@Wghs); c_gate = sigmoid(s@Wgvc + h@Wghc)
// ---------------------------------------------------------------------------
__global__ void gates_kernel(const float* __restrict__ hiddens,
                             const float* __restrict__ Wgvs,
                             const float* __restrict__ Wghs,
                             const float* __restrict__ Wgvc,
                             const float* __restrict__ Wghc) {
    __shared__ float As[8][64];
    const int n0 = blockIdx.x * 64, m0 = blockIdx.y * 8;
    const int col = n0 + (threadIdx.x & 63);
    const int rl  = (threadIdx.x >> 6) * 2;
    const int r0  = m0 + rl;
    float a0s = 0.f, a1s = 0.f, a0c = 0.f, a1c = 0.f;
    for (int phase = 0; phase < 2; ++phase) {
        const float* A   = phase ? hiddens : g_s;
        const float* Wsp = phase ? Wghs : Wgvs;
        const float* Wcp = phase ? Wghc : Wgvc;
        for (int k0 = 0; k0 < 512; k0 += 64) {
            __syncthreads();
            for (int i = threadIdx.x; i < 512; i += 256) {
                int r = m0 + (i >> 6), kk = i & 63;
                As[i >> 6][kk] = A[r * 512 + k0 + kk];
            }
            __syncthreads();
            #pragma unroll 8
            for (int kk = 0; kk < 64; kk++) {
                float ws = Wsp[(k0 + kk) * 512 + col];
                float wc = Wcp[(k0 + kk) * 512 + col];
                float v0 = As[rl][kk], v1 = As[rl + 1][kk];
                a0s += v0 * ws; a1s += v1 * ws;
                a0c += v0 * wc; a1c += v1 * wc;
            }
        }
    }
    g_sgate[r0 * 512 + col]       = sigmoidf_(a0s);
    g_sgate[(r0 + 1) * 512 + col] = sigmoidf_(a1s);
    g_cgate[r0 * 512 + col]       = sigmoidf_(a0c);
    g_cgate[(r0 + 1) * 512 + col] = sigmoidf_(a1c);
}

// ---------------------------------------------------------------------------
// chat = sgate*(cspat@Wspat) + cgate*(cchan@Wchan) + h
// ---------------------------------------------------------------------------
__global__ void chat_kernel(const float* __restrict__ hiddens,
                            const float* __restrict__ Wspat,
                            const float* __restrict__ Wchan) {
    __shared__ float As[8][64];
    __shared__ float Cc[8][49];
    const int n0 = blockIdx.x * 64, m0 = blockIdx.y * 8;
    const int col = n0 + (threadIdx.x & 63);
    const int rl  = (threadIdx.x >> 6) * 2;
    const int r0  = m0 + rl;
    float a0 = 0.f, a1 = 0.f;
    for (int k0 = 0; k0 < CDIM; k0 += 64) {
        __syncthreads();
        for (int i = threadIdx.x; i < 512; i += 256) {
            int r = m0 + (i >> 6), kk = i & 63;
            As[i >> 6][kk] = g_cspat[r * CDIM + k0 + kk];
        }
        __syncthreads();
        #pragma unroll 8
        for (int kk = 0; kk < 64; kk++) {
            float w = Wspat[(k0 + kk) * 512 + col];
            a0 += As[rl][kk] * w;
            a1 += As[rl + 1][kk] * w;
        }
    }
    __syncthreads();
    for (int i = threadIdx.x; i < 8 * NPIX; i += 256)
        Cc[i / NPIX][i % NPIX] = g_cchan[(m0 + i / NPIX) * NPIX + i % NPIX];
    __syncthreads();
    float b0 = 0.f, b1 = 0.f;
    for (int k = 0; k < NPIX; k++) {
        float w = Wchan[k * 512 + col];
        b0 += Cc[rl][k] * w;
        b1 += Cc[rl + 1][k] * w;
    }
    g_chat[r0 * 512 + col] =
        g_sgate[r0 * 512 + col] * a0 + g_cgate[r0 * 512 + col] * b0 + hiddens[r0 * 512 + col];
    g_chat[(r0 + 1) * 512 + col] =
        g_sgate[(r0 + 1) * 512 + col] * a1 + g_cgate[(r0 + 1) * 512 + col] * b1 + hiddens[(r0 + 1) * 512 + col];
}

// ---------------------------------------------------------------------------
// scores = chat @ Wmlp + bmlp      [64, 10000]
// grid 157 blocks; TM=64, TN=64, thread: 2 cols x 8 rows.
// ---------------------------------------------------------------------------
__global__ void scores_kernel(const float* __restrict__ Wmlp,
                              const float* __restrict__ bmlp,
                              float* __restrict__ out) {
    __shared__ float As[64][33];
    const int n0 = blockIdx.x * 64;
    const int cid = threadIdx.x & 31, rid = threadIdx.x >> 5;
    const int c0 = n0 + cid * 2, c1 = c0 + 1;
    const int cc0 = min(c0, VOCAB - 1), cc1 = min(c1, VOCAB - 1);
    float acc[8][2];
    #pragma unroll
    for (int r = 0; r < 8; r++) { acc[r][0] = 0.f; acc[r][1] = 0.f; }
    for (int k0 = 0; k0 < 512; k0 += 32) {
        __syncthreads();
        for (int i = threadIdx.x; i < 2048; i += 256) {
            int r = i >> 5, kk = i & 31;
            As[r][kk] = g_chat[r * 512 + k0 + kk];
        }
        __syncthreads();
        #pragma unroll 4
        for (int kk = 0; kk < 32; kk++) {
            float w0 = Wmlp[(size_t)(k0 + kk) * VOCAB + cc0];
            float w1 = Wmlp[(size_t)(k0 + kk) * VOCAB + cc1];
            #pragma unroll
            for (int r = 0; r < 8; r++) {
                float a = As[rid * 8 + r][kk];
                acc[r][0] += a * w0;
                acc[r][1] += a * w1;
            }
        }
    }
    if (c0 < VOCAB) {
        float bb = bmlp[c0];
        #pragma unroll
        for (int r = 0; r < 8; r++) out[(size_t)(rid * 8 + r) * VOCAB + c0] = acc[r][0] + bb;
    }
    if (c1 < VOCAB) {
        float bb = bmlp[c1];
        #pragma unroll
        for (int r = 0; r < 8; r++) out[(size_t)(rid * 8 + r) * VOCAB + c1] = acc[r][1] + bb;
    }
}

// ---------------------------------------------------------------------------
extern "C" void kernel_launch(void* const* d_in, const int* in_sizes, int n_in,
                              void* d_out, int out_size) {
    (void)in_sizes; (void)n_in; (void)out_size;
    const float* x       = (const float*)d_in[0];
    const float* hiddens = (const float*)d_in[1];
    const float* cells   = (const float*)d_in[2];
    const float* V       = (const float*)d_in[3];
    const float* Wsx     = (const float*)d_in[4];
    const float* Wsh     = (const float*)d_in[5];
    const float* Wv      = (const float*)d_in[6];
    const float* Wg      = (const float*)d_in[7];
    const float* Ws      = (const float*)d_in[8];
    const float* Wh      = (const float*)d_in[9];
    const float* Wfeat   = (const float*)d_in[10];
    const float* Wcxt    = (const float*)d_in[11];
    const float* Wg2     = (const float*)d_in[12];
    const float* Wspat   = (const float*)d_in[13];
    const float* Wchan   = (const float*)d_in[14];
    const float* Wgvs    = (const float*)d_in[15];
    const float* Wgvc    = (const float*)d_in[16];
    const float* Wghs    = (const float*)d_in[17];
    const float* Wghc    = (const float*)d_in[18];
    const float* Wmlp    = (const float*)d_in[19];
    const float* bmlp    = (const float*)d_in[20];

    float* out        = (float*)d_out;
    float* out_scores = out;                          // 64*10000
    float* out_alpha  = out + BT * VOCAB;             // 64*49
    float* out_beta   = out + BT * VOCAB + BT * NPIX; // 64

    s_kernel<<<dim3(8, 8), 256>>>(x, hiddens, cells, Wsx, Wsh);
    g2_kernel<<<dim3(8, 8), 256>>>(hiddens, Wg2);
    featmean_kernel<<<64, 256>>>(V);
    cxt_kernel<<<dim3(64, 4), 256>>>(Wfeat, Wcxt);
    softmax2048_kernel<<<64, 256>>>();
    gcs_kernel<<<64, 64>>>(hiddens, Wg, Ws);
    wfwv_kernel<<<dim3(64, DSPLIT), 224>>>(V, Wv);
    cchan_kernel<<<64, 256>>>(V);
    zt_kernel<<<64, 64>>>(Wh, out_alpha, out_beta);
    cspatial_kernel<<<dim3(64, 8), 256>>>(V);
    gates_kernel<<<dim3(8, 8), 256>>>(hiddens, Wgvs, Wghs, Wgvc, Wghc);
    chat_kernel<<<dim3(8, 8), 256>>>(hiddens, Wspat, Wchan);
    scores_kernel<<<157, 256>>>(Wmlp, bmlp, out_scores);
}

// round 3
// speedup vs baseline: 1.5515x; 1.5515x over previous
#include <cuda_runtime.h>
#include <math.h>

#define BT    64
#define NPIX  49
#define CDIM  2048
#define VOCAB 10000

// ---------------- scratch ----------------
__device__ float g_s[BT*512];
__device__ float g_g2[BT*512];
__device__ float g_fm[8*CDIM];
__device__ float g_alpha0[BT*CDIM];
__device__ float g_Mpart[4*BT*NPIX*NPIX];
__device__ float g_cchanp[4*BT*NPIX];
__device__ float g_alpha_t[BT*NPIX];
__device__ float g_cspat[BT*CDIM];
__device__ float g_sgate[BT*512];
__device__ float g_cgate[BT*512];
__device__ float g_spart[4*BT*512];
__device__ float g_chat[BT*512];

__device__ __forceinline__ float tanh_fast(float x) {
    float y;
    asm("tanh.approx.f32 %0, %1;" : "=f"(y) : "f"(x));
    return y;
}
__device__ __forceinline__ float sigmoidf_(float x) {
    return 1.0f / (1.0f + expf(-x));
}

// ---------------------------------------------------------------------------
// featmean[b,d] = mean_k V[b,k,d]
// ---------------------------------------------------------------------------
__global__ void featmean_kernel(const float* __restrict__ V) {
    int idx = blockIdx.x * 256 + threadIdx.x;
    int b = idx >> 11, d = idx & 2047;
    float s = 0.f;
    #pragma unroll 7
    for (int k = 0; k < NPIX; k++) s += V[(b * NPIX + k) * CDIM + d];
    g_fm[idx] = s * (1.0f / 49.0f);
}

// ---------------------------------------------------------------------------
// z=0: s = sigmoid(x@Wsx + hprev@Wsh)*tanh(cells);  z=1: g2 = h@Wg2
// grid (16 colTiles of 32, 4 rowTiles of 16, 2), 256 thr, 2 rows/thread
// ---------------------------------------------------------------------------
__global__ void pre_kernel(const float* __restrict__ x,
                           const float* __restrict__ hiddens,
                           const float* __restrict__ cells,
                           const float* __restrict__ Wsx,
                           const float* __restrict__ Wsh,
                           const float* __restrict__ Wg2) {
    __shared__ __align__(16) float As[16][64];
    const int op = blockIdx.z;
    const int n0 = blockIdx.x * 32, m0 = blockIdx.y * 16;
    const int col = n0 + (threadIdx.x & 31);
    const int rl  = (threadIdx.x >> 5) * 2;
    const int r0  = m0 + rl;
    float acc0 = 0.f, acc1 = 0.f;
    const int nph = (op == 0) ? 2 : 1;
    for (int phase = 0; phase < nph; ++phase) {
        const float* W = (op == 0) ? (phase ? Wsh : Wsx) : Wg2;
        for (int k0 = 0; k0 < 512; k0 += 64) {
            __syncthreads();
            for (int i = threadIdx.x; i < 1024; i += 256) {
                int r = m0 + (i >> 6), kk = i & 63;
                float v;
                if (op == 0 && phase == 1) v = (r & 7) ? hiddens[(r - 1) * 512 + k0 + kk] : 0.f;
                else if (op == 0)          v = x[r * 512 + k0 + kk];
                else                       v = hiddens[r * 512 + k0 + kk];
                As[i >> 6][kk] = v;
            }
            __syncthreads();
            #pragma unroll 8
            for (int kk = 0; kk < 64; kk++) {
                float w = W[(k0 + kk) * 512 + col];
                acc0 += As[rl][kk]     * w;
                acc1 += As[rl + 1][kk] * w;
            }
        }
    }
    if (op == 0) {
        g_s[r0 * 512 + col]       = sigmoidf_(acc0) * tanhf(cells[r0 * 512 + col]);
        g_s[(r0 + 1) * 512 + col] = sigmoidf_(acc1) * tanhf(cells[(r0 + 1) * 512 + col]);
    } else {
        g_g2[r0 * 512 + col]       = acc0;
        g_g2[(r0 + 1) * 512 + col] = acc1;
    }
}

// ---------------------------------------------------------------------------
// cxt (unnormalized alpha0): 128 thr x 4 d, grid (64 bt, 4 chunks of 512)
// ---------------------------------------------------------------------------
__global__ void cxt_kernel(const float* __restrict__ Wfeat,
                           const float* __restrict__ Wcxt) {
    __shared__ __align__(16) float wf[512];
    __shared__ __align__(16) float wc[512];
    __shared__ __align__(16) float gr[512];
    const int bt = blockIdx.x, b = bt >> 3;
    for (int i = threadIdx.x; i < 512; i += 128) {
        wf[i] = Wfeat[i];
        wc[i] = Wcxt[i];
        gr[i] = g_g2[bt * 512 + i];
    }
    __syncthreads();
    const int d0 = blockIdx.y * 512 + threadIdx.x;
    float a0 = g_fm[b * CDIM + d0];
    float a1 = g_fm[b * CDIM + d0 + 128];
    float a2 = g_fm[b * CDIM + d0 + 256];
    float a3 = g_fm[b * CDIM + d0 + 384];
    float c0 = 0.f, c1 = 0.f, c2 = 0.f, c3 = 0.f;
    #pragma unroll 4
    for (int j = 0; j < 512; j++) {
        float wfj = wf[j], grj = gr[j], wcj = wc[j];
        c0 += tanh_fast(fmaf(a0, wfj, grj)) * wcj;
        c1 += tanh_fast(fmaf(a1, wfj, grj)) * wcj;
        c2 += tanh_fast(fmaf(a2, wfj, grj)) * wcj;
        c3 += tanh_fast(fmaf(a3, wfj, grj)) * wcj;
    }
    g_alpha0[bt * CDIM + d0]       = c0;
    g_alpha0[bt * CDIM + d0 + 128] = c1;
    g_alpha0[bt * CDIM + d0 + 256] = c2;
    g_alpha0[bt * CDIM + d0 + 384] = c3;
}

// ---------------------------------------------------------------------------
// softmax over 2048 per bt (in place)
// ---------------------------------------------------------------------------
__global__ void softmax2048_kernel() {
    __shared__ float red[256];
    const int bt = blockIdx.x, t = threadIdx.x;
    float* p = g_alpha0 + bt * CDIM;
    float mx = -1e30f;
    for (int i = t; i < CDIM; i += 256) mx = fmaxf(mx, p[i]);
    red[t] = mx; __syncthreads();
    for (int s = 128; s > 0; s >>= 1) { if (t < s) red[t] = fmaxf(red[t], red[t + s]); __syncthreads(); }
    mx = red[0]; __syncthreads();
    float sm = 0.f;
    for (int i = t; i < CDIM; i += 256) { float e = __expf(p[i] - mx); p[i] = e; sm += e; }
    red[t] = sm; __syncthreads();
    for (int s = 128; s > 0; s >>= 1) { if (t < s) red[t] += red[t + s]; __syncthreads(); }
    float inv = 1.0f / red[0];
    for (int i = t; i < CDIM; i += 256) p[i] *= inv;
}

// ---------------------------------------------------------------------------
// wfwv: M partials + cchan partials. grid (64 bt, 4 dp), 192 thr.
// 13x13 active threads, 4x4 register tiles; threads 169..191 do cchan rows.
// ---------------------------------------------------------------------------
__global__ void wfwv_kernel(const float* __restrict__ V,
                            const float* __restrict__ Wv) {
    __shared__ __align__(16) float Wvs[64][52];   // 52*4B row stride: 16B-aligned rows
    __shared__ __align__(16) float aV[49][65];
    __shared__ __align__(16) float as_[512];
    const int bt = blockIdx.x, b = bt >> 3;
    const int dp = blockIdx.y, d0 = dp * 512;
    const int t = threadIdx.x;
    for (int i = t; i < 512; i += 192) as_[i] = g_alpha0[bt * CDIM + d0 + i];
    if (t < 64) { Wvs[t][49] = 0.f; Wvs[t][50] = 0.f; Wvs[t][51] = 0.f; }
    const int tk = t / 13, tk2 = t % 13;
    const bool active = (t < 169);
    int ki[4];
    #pragma unroll
    for (int i = 0; i < 4; i++) ki[i] = min(tk * 4 + i, 48);
    float acc[4][4];
    #pragma unroll
    for (int i = 0; i < 4; i++)
        #pragma unroll
        for (int j = 0; j < 4; j++) acc[i][j] = 0.f;
    float chs0 = 0.f, chs1 = 0.f, chs2 = 0.f;
    const int crow = t - 169;  // 0..22 for helper threads
    for (int c = 0; c < 8; c++) {
        __syncthreads();
        for (int i = t; i < 49 * 64; i += 192) {
            int r = i >> 6, dd = i & 63;
            aV[r][dd] = V[(b * NPIX + r) * CDIM + d0 + c * 64 + dd] * as_[c * 64 + dd];
        }
        for (int i = t; i < 64 * 49; i += 192) {
            Wvs[i / 49][i % 49] = Wv[(size_t)(d0 + c * 64) * NPIX + i];
        }
        __syncthreads();
        if (active) {
            #pragma unroll 4
            for (int dd = 0; dd < 64; dd++) {
                const float4 wv = *reinterpret_cast<const float4*>(&Wvs[dd][tk2 * 4]);
                float av0 = aV[ki[0]][dd], av1 = aV[ki[1]][dd];
                float av2 = aV[ki[2]][dd], av3 = aV[ki[3]][dd];
                acc[0][0] += av0 * wv.x; acc[0][1] += av0 * wv.y; acc[0][2] += av0 * wv.z; acc[0][3] += av0 * wv.w;
                acc[1][0] += av1 * wv.x; acc[1][1] += av1 * wv.y; acc[1][2] += av1 * wv.z; acc[1][3] += av1 * wv.w;
                acc[2][0] += av2 * wv.x; acc[2][1] += av2 * wv.y; acc[2][2] += av2 * wv.z; acc[2][3] += av2 * wv.w;
                acc[3][0] += av3 * wv.x; acc[3][1] += av3 * wv.y; acc[3][2] += av3 * wv.z; acc[3][3] += av3 * wv.w;
            }
        } else {
            // cchan partial rows: crow, crow+23, crow+46
            float s0 = 0.f, s1 = 0.f, s2 = 0.f;
            #pragma unroll 8
            for (int dd = 0; dd < 64; dd++) {
                s0 += aV[crow][dd];
                if (crow + 23 < 49) s1 += aV[crow + 23][dd];
                if (crow + 46 < 49) s2 += aV[crow + 46][dd];
            }
            chs0 += s0; chs1 += s1; chs2 += s2;
        }
    }
    if (active) {
        #pragma unroll
        for (int i = 0; i < 4; i++) {
            int k = tk * 4 + i;
            if (k >= NPIX) continue;
            #pragma unroll
            for (int j = 0; j < 4; j++) {
                int k2 = tk2 * 4 + j;
                if (k2 < NPIX)
                    g_Mpart[(((size_t)dp * BT + bt) * NPIX + k) * NPIX + k2] = acc[i][j];
            }
        }
    } else {
        g_cchanp[(dp * BT + bt) * NPIX + crow] = chs0;
        if (crow + 23 < 49) g_cchanp[(dp * BT + bt) * NPIX + crow + 23] = chs1;
        if (crow + 46 < 49) g_cchanp[(dp * BT + bt) * NPIX + crow + 46] = chs2;
    }
}

// ---------------------------------------------------------------------------
// zt: fused gcs + z_t + softmaxes. grid 64 blocks x 64 thr.
// ---------------------------------------------------------------------------
__global__ void zt_kernel(const float* __restrict__ hiddens,
                          const float* __restrict__ Wg,
                          const float* __restrict__ Ws,
                          const float* __restrict__ Wh,
                          float* __restrict__ out_alpha,
                          float* __restrict__ out_beta) {
    __shared__ float h_sm[512], s_sm[512];
    __shared__ float Msum[NPIX * NPIX];
    __shared__ float gg[NPIX], css[NPIX], wh[NPIX], ztv[NPIX];
    const int bt = blockIdx.x, t = threadIdx.x;
    for (int i = t; i < 512; i += 64) {
        h_sm[i] = hiddens[bt * 512 + i];
        s_sm[i] = g_s[bt * 512 + i];
    }
    if (t < NPIX) wh[t] = Wh[t];
    {
        const float* p0 = g_Mpart + (size_t)bt * NPIX * NPIX;
        const float* p1 = p0 + (size_t)BT * NPIX * NPIX;
        const float* p2 = p1 + (size_t)BT * NPIX * NPIX;
        const float* p3 = p2 + (size_t)BT * NPIX * NPIX;
        for (int i = t; i < NPIX * NPIX; i += 64)
            Msum[i] = p0[i] + p1[i] + p2[i] + p3[i];
    }
    __syncthreads();
    if (t < NPIX) {
        float ggv = 0.f, ssv = 0.f;
        #pragma unroll 8
        for (int k = 0; k < 512; k++) {
            ggv += h_sm[k] * Wg[k * NPIX + t];
            ssv += s_sm[k] * Ws[k * NPIX + t];
        }
        gg[t] = ggv;
        css[t] = ssv + ggv;
    }
    __syncthreads();
    if (t < NPIX) {
        float z = 0.f;
        #pragma unroll 7
        for (int k2 = 0; k2 < NPIX; k2++)
            z += tanh_fast(tanh_fast(Msum[t * NPIX + k2] + gg[k2])) * wh[k2];
        ztv[t] = z;
    }
    __syncthreads();
    if (t == 0) {
        float ze = 0.f;
        for (int k = 0; k < NPIX; k++) ze += tanh_fast(css[k]) * wh[k];
        float mx = -1e30f;
        for (int k = 0; k < NPIX; k++) mx = fmaxf(mx, ztv[k]);
        float sm = 0.f;
        for (int k = 0; k < NPIX; k++) sm += __expf(ztv[k] - mx);
        float inv = 1.0f / sm;
        for (int k = 0; k < NPIX; k++) {
            float a = __expf(ztv[k] - mx) * inv;
            g_alpha_t[bt * NPIX + k] = a;
            out_alpha[bt * NPIX + k] = a;
        }
        float mx2 = fmaxf(mx, ze);
        float sm2 = 0.f;
        for (int k = 0; k < NPIX; k++) sm2 += __expf(ztv[k] - mx2);
        sm2 += __expf(ze - mx2);
        out_beta[bt] = __expf(ze - mx2) / sm2;
    }
}

// ---------------------------------------------------------------------------
// c_spatial[bt,d] = sum_k alpha_t[bt,k] * V[b,k,d]   grid (64, 8) x 256
// ---------------------------------------------------------------------------
__global__ void cspatial_kernel(const float* __restrict__ V) {
    __shared__ float al[NPIX];
    const int bt = blockIdx.x, b = bt >> 3;
    if (threadIdx.x < NPIX) al[threadIdx.x] = g_alpha_t[bt * NPIX + threadIdx.x];
    __syncthreads();
    const int d = blockIdx.y * 256 + threadIdx.x;
    float s = 0.f;
    #pragma unroll 7
    for (int k = 0; k < NPIX; k++) s += al[k] * V[(b * NPIX + k) * CDIM + d];
    g_cspat[bt * CDIM + d] = s;
}

// ---------------------------------------------------------------------------
// gates: z=0 -> sgate (Wgvs/Wghs), z=1 -> cgate (Wgvc/Wghc)
// grid (16,4,2), 256 thr, tile 16x32
// ---------------------------------------------------------------------------
__global__ void gates_kernel(const float* __restrict__ hiddens,
                             const float* __restrict__ Wgvs,
                             const float* __restrict__ Wghs,
                             const float* __restrict__ Wgvc,
                             const float* __restrict__ Wghc) {
    __shared__ __align__(16) float As[16][64];
    const int op = blockIdx.z;
    const int n0 = blockIdx.x * 32, m0 = blockIdx.y * 16;
    const int col = n0 + (threadIdx.x & 31);
    const int rl  = (threadIdx.x >> 5) * 2;
    const int r0  = m0 + rl;
    float acc0 = 0.f, acc1 = 0.f;
    for (int phase = 0; phase < 2; ++phase) {
        const float* A = phase ? hiddens : g_s;
        const float* W = phase ? (op ? Wghc : Wghs) : (op ? Wgvc : Wgvs);
        for (int k0 = 0; k0 < 512; k0 += 64) {
            __syncthreads();
            for (int i = threadIdx.x; i < 1024; i += 256) {
                int r = m0 + (i >> 6), kk = i & 63;
                As[i >> 6][kk] = A[r * 512 + k0 + kk];
            }
            __syncthreads();
            #pragma unroll 8
            for (int kk = 0; kk < 64; kk++) {
                float w = W[(k0 + kk) * 512 + col];
                acc0 += As[rl][kk]     * w;
                acc1 += As[rl + 1][kk] * w;
            }
        }
    }
    float* out = op ? g_cgate : g_sgate;
    out[r0 * 512 + col]       = sigmoidf_(acc0);
    out[(r0 + 1) * 512 + col] = sigmoidf_(acc1);
}

// ---------------------------------------------------------------------------
// spat partial: g_spart[z] = cspat[:, z*512:(z+1)*512] @ Wspat[z*512:...]
// grid (16,4,4), 256 thr, tile 16x32
// ---------------------------------------------------------------------------
__global__ void spatpart_kernel(const float* __restrict__ Wspat) {
    __shared__ __align__(16) float As[16][64];
    const int zc = blockIdx.z, kb = zc * 512;
    const int n0 = blockIdx.x * 32, m0 = blockIdx.y * 16;
    const int col = n0 + (threadIdx.x & 31);
    const int rl  = (threadIdx.x >> 5) * 2;
    const int r0  = m0 + rl;
    float acc0 = 0.f, acc1 = 0.f;
    for (int k0 = 0; k0 < 512; k0 += 64) {
        __syncthreads();
        for (int i = threadIdx.x; i < 1024; i += 256) {
            int r = m0 + (i >> 6), kk = i & 63;
            As[i >> 6][kk] = g_cspat[r * CDIM + kb + k0 + kk];
        }
        __syncthreads();
        #pragma unroll 8
        for (int kk = 0; kk < 64; kk++) {
            float w = Wspat[(size_t)(kb + k0 + kk) * 512 + col];
            acc0 += As[rl][kk]     * w;
            acc1 += As[rl + 1][kk] * w;
        }
    }
    g_spart[(zc * BT + r0) * 512 + col]       = acc0;
    g_spart[(zc * BT + r0 + 1) * 512 + col]   = acc1;
}

// ---------------------------------------------------------------------------
// combine: g_chat = sgate*spat + cgate*(cchan@Wchan) + h.  64 blocks x 512.
// ---------------------------------------------------------------------------
__global__ void combine_kernel(const float* __restrict__ hiddens,
                               const float* __restrict__ Wchan) {
    __shared__ float ch[NPIX];
    const int r = blockIdx.x, c = threadIdx.x;
    if (c < NPIX) {
        float v = g_cchanp[r * NPIX + c]
                + g_cchanp[(BT + r) * NPIX + c]
                + g_cchanp[(2 * BT + r) * NPIX + c]
                + g_cchanp[(3 * BT + r) * NPIX + c];
        ch[c] = v * (1.0f / 2048.0f);
    }
    __syncthreads();
    float spat = g_spart[r * 512 + c]
               + g_spart[(BT + r) * 512 + c]
               + g_spart[(2 * BT + r) * 512 + c]
               + g_spart[(3 * BT + r) * 512 + c];
    float cb = 0.f;
    #pragma unroll 7
    for (int k = 0; k < NPIX; k++) cb += ch[k] * Wchan[k * 512 + c];
    g_chat[r * 512 + c] = g_sgate[r * 512 + c] * spat
                        + g_cgate[r * 512 + c] * cb
                        + hiddens[r * 512 + c];
}

// ---------------------------------------------------------------------------
// scores = chat @ Wmlp + bmlp.  grid 139 (single wave), 288 thr,
// tile 64 rows x 72 cols; thread = 2 cols x 8 rows, float2 weight loads.
// ---------------------------------------------------------------------------
__global__ void scores_kernel(const float* __restrict__ Wmlp,
                              const float* __restrict__ bmlp,
                              float* __restrict__ out) {
    __shared__ __align__(16) float As[64][33];
    const int n0 = blockIdx.x * 72;
    const int rid = threadIdx.x / 36;
    const int cid = threadIdx.x - rid * 36;
    const int c0 = n0 + cid * 2, c1 = c0 + 1;
    const bool full = (n0 + 71 < VOCAB);
    float acc[8][2];
    #pragma unroll
    for (int r = 0; r < 8; r++) { acc[r][0] = 0.f; acc[r][1] = 0.f; }
    for (int k0 = 0; k0 < 512; k0 += 32) {
        __syncthreads();
        for (int i = threadIdx.x; i < 2048; i += 288) {
            int r = i >> 5, kk = i & 31;
            As[r][kk] = g_chat[r * 512 + k0 + kk];
        }
        __syncthreads();
        if (full) {
            #pragma unroll 4
            for (int kk = 0; kk < 32; kk++) {
                const float2 w = *reinterpret_cast<const float2*>(
                    &Wmlp[(size_t)(k0 + kk) * VOCAB + c0]);
                #pragma unroll
                for (int r = 0; r < 8; r++) {
                    float a = As[rid * 8 + r][kk];
                    acc[r][0] += a * w.x;
                    acc[r][1] += a * w.y;
                }
            }
        } else {
            #pragma unroll 4
            for (int kk = 0; kk < 32; kk++) {
                float w0 = (c0 < VOCAB) ? Wmlp[(size_t)(k0 + kk) * VOCAB + c0] : 0.f;
                float w1 = (c1 < VOCAB) ? Wmlp[(size_t)(k0 + kk) * VOCAB + c1] : 0.f;
                #pragma unroll
                for (int r = 0; r < 8; r++) {
                    float a = As[rid * 8 + r][kk];
                    acc[r][0] += a * w0;
                    acc[r][1] += a * w1;
                }
            }
        }
    }
    if (c0 < VOCAB) {
        float bb = bmlp[c0];
        #pragma unroll
        for (int r = 0; r < 8; r++) out[(size_t)(rid * 8 + r) * VOCAB + c0] = acc[r][0] + bb;
    }
    if (c1 < VOCAB) {
        float bb = bmlp[c1];
        #pragma unroll
        for (int r = 0; r < 8; r++) out[(size_t)(rid * 8 + r) * VOCAB + c1] = acc[r][1] + bb;
    }
}

// ---------------------------------------------------------------------------
extern "C" void kernel_launch(void* const* d_in, const int* in_sizes, int n_in,
                              void* d_out, int out_size) {
    (void)in_sizes; (void)n_in; (void)out_size;
    const float* x       = (const float*)d_in[0];
    const float* hiddens = (const float*)d_in[1];
    const float* cells   = (const float*)d_in[2];
    const float* V       = (const float*)d_in[3];
    const float* Wsx     = (const float*)d_in[4];
    const float* Wsh     = (const float*)d_in[5];
    const float* Wv      = (const float*)d_in[6];
    const float* Wg      = (const float*)d_in[7];
    const float* Ws      = (const float*)d_in[8];
    const float* Wh      = (const float*)d_in[9];
    const float* Wfeat   = (const float*)d_in[10];
    const float* Wcxt    = (const float*)d_in[11];
    const float* Wg2     = (const float*)d_in[12];
    const float* Wspat   = (const float*)d_in[13];
    const float* Wchan   = (const float*)d_in[14];
    const float* Wgvs    = (const float*)d_in[15];
    const float* Wgvc    = (const float*)d_in[16];
    const float* Wghs    = (const float*)d_in[17];
    const float* Wghc    = (const float*)d_in[18];
    const float* Wmlp    = (const float*)d_in[19];
    const float* bmlp    = (const float*)d_in[20];

    float* out        = (float*)d_out;
    float* out_scores = out;
    float* out_alpha  = out + BT * VOCAB;
    float* out_beta   = out + BT * VOCAB + BT * NPIX;

    featmean_kernel<<<64, 256>>>(V);
    pre_kernel<<<dim3(16, 4, 2), 256>>>(x, hiddens, cells, Wsx, Wsh, Wg2);
    cxt_kernel<<<dim3(64, 4), 128>>>(Wfeat, Wcxt);
    softmax2048_kernel<<<64, 256>>>();
    wfwv_kernel<<<dim3(64, 4), 192>>>(V, Wv);
    zt_kernel<<<64, 64>>>(hiddens, Wg, Ws, Wh, out_alpha, out_beta);
    cspatial_kernel<<<dim3(64, 8), 256>>>(V);
    gates_kernel<<<dim3(16, 4, 2), 256>>>(hiddens, Wgvs, Wghs, Wgvc, Wghc);
    spatpart_kernel<<<dim3(16, 4, 4), 256>>>(Wspat);
    combine_kernel<<<64, 512>>>(hiddens, Wchan);
    scores_kernel<<<139, 288>>>(Wmlp, bmlp, out_scores);
}